// round 10
// baseline (speedup 1.0000x reference)
#include <cuda_runtime.h>

#define BATCH  4
#define NPTS   8192
#define TOTAL  (BATCH * NPTS)
#define NB     1024
#define NSEG   8                  // segments per (array,batch), 1024 pts each
#define XMIN   (-5.0f)
#define BH     (10.0f / (float)NB)
#define INVH   ((float)NB / 10.0f)

#define QB       256     // queries per nn block
#define CWIN     1280    // candidate window (smem) per block
#define NTHREADS 256     // nn threads: 1 query per thread, 2 accumulators

#define FB_BLOCKS  256
#define FB_THREADS 256
#define FB_WARPS   (FB_BLOCKS * FB_THREADS / 32)

#define SCALE (1.0f / (float)TOTAL)

// Scratch (__device__ globals — no allocation allowed):
__device__ float4 g_sorted[2][TOTAL];          // (x,y,z,|p|^2), bucket-sorted by x
__device__ int    g_seghist[8][NSEG][NB];      // per-(ab, segment) bucket counts
__device__ int    g_segbase[8][NSEG][NB];      // scatter base per (ab, segment, bucket)
__device__ int    g_off[2][BATCH][NB + 1];     // bucket prefix offsets
__device__ float  g_best[2][TOTAL];            // window bound for failed queries
__device__ int    g_nfail;
__device__ int    g_fail[2 * TOTAL];

__device__ __forceinline__ int bucket_of(float x) {
    int b = (int)floorf((x - XMIN) * INVH);
    return min(max(b, 0), NB - 1);
}

// grid (NSEG, 8 ab-pairs) x 1024: smem histogram per segment.
__global__ __launch_bounds__(1024) void hist_kernel(const float* __restrict__ p1,
                                                    const float* __restrict__ p2) {
    __shared__ int s[NB];
    const int ab = blockIdx.y;
    const int a = ab >> 2, b = ab & 3;
    const float* __restrict__ src = (a ? p2 : p1) + (b * NPTS + blockIdx.x * 1024) * 3;
    const int t = threadIdx.x;

    s[t] = 0;
    __syncthreads();
    atomicAdd(&s[bucket_of(src[3 * t])], 1);
    __syncthreads();
    g_seghist[ab][blockIdx.x][t] = s[t];
}

// One block per ab: per-bucket totals across segments -> block scan -> segment bases.
__global__ __launch_bounds__(1024) void scan_kernel(float* __restrict__ out) {
    __shared__ int wsum[32];
    const int ab = blockIdx.x;
    const int a = ab >> 2, b = ab & 3;
    const int t = threadIdx.x;
    const int lane = t & 31, warp = t >> 5;

    int segc[NSEG];
    int cnt = 0;
    #pragma unroll
    for (int s = 0; s < NSEG; s++) {
        segc[s] = g_seghist[ab][s][t];
        cnt += segc[s];
    }

    int v = cnt;
    #pragma unroll
    for (int o = 1; o < 32; o <<= 1) {
        int u = __shfl_up_sync(0xffffffffu, v, o);
        if (lane >= o) v += u;
    }
    if (lane == 31) wsum[warp] = v;
    __syncthreads();
    if (t < 32) {
        int w = wsum[t];
        #pragma unroll
        for (int o = 1; o < 32; o <<= 1) {
            int u = __shfl_up_sync(0xffffffffu, w, o);
            if (t >= o) w += u;
        }
        wsum[t] = w;
    }
    __syncthreads();
    const int incl = v + (warp ? wsum[warp - 1] : 0);
    int base = incl - cnt;                 // exclusive bucket base
    g_off[a][b][t] = base;
    if (t == NB - 1) g_off[a][b][NB] = incl;
    if (ab == 0 && t == 0) { g_nfail = 0; out[0] = 0.0f; }

    #pragma unroll
    for (int s = 0; s < NSEG; s++) {
        g_segbase[ab][s][t] = base;
        base += segc[s];
    }
}

// grid (NSEG, 8 ab) x 1024: rank via smem atomics over precomputed segment bases.
__global__ __launch_bounds__(1024) void scatter_kernel(const float* __restrict__ p1,
                                                       const float* __restrict__ p2) {
    __shared__ int cur[NB];
    const int ab = blockIdx.y;
    const int a = ab >> 2, b = ab & 3;
    const float* __restrict__ src = (a ? p2 : p1) + (b * NPTS + blockIdx.x * 1024) * 3;
    const int t = threadIdx.x;

    cur[t] = g_segbase[ab][blockIdx.x][t];
    __syncthreads();

    float x = src[3 * t], y = src[3 * t + 1], z = src[3 * t + 2];
    float w = fmaf(x, x, fmaf(y, y, z * z));
    int pos = atomicAdd(&cur[bucket_of(x)], 1);
    g_sorted[a][b * NPTS + pos] = make_float4(x, y, z, w);
}

// grid (NPTS/QB, BATCH, 2). 1 query/thread, 2 alternating min accumulators.
__global__ __launch_bounds__(NTHREADS) void nn_kernel(float* __restrict__ out) {
    __shared__ float4 sc[CWIN];    // 20 KB
    __shared__ int s_c0;
    __shared__ float spart[NTHREADS / 32];

    const int dir = blockIdx.z;
    const int b   = blockIdx.y;
    const int qbase = blockIdx.x * QB;
    const int tid = threadIdx.x;
    const int lane = tid & 31, warp = tid >> 5;

    const float4* __restrict__ qs   = &g_sorted[dir][b * NPTS] + qbase;
    const float4* __restrict__ cand = &g_sorted[dir ^ 1][b * NPTS];
    const int*    __restrict__ off  = g_off[dir ^ 1][b];

    if (tid == 0) {
        int c0 = off[bucket_of(qs[QB / 2].x)] - CWIN / 2;
        s_c0 = max(0, min(c0, NPTS - CWIN));
    }
    __syncthreads();
    const int c0 = s_c0;

    #pragma unroll
    for (int j = tid; j < CWIN; j += NTHREADS)
        sc[j] = cand[c0 + j];
    __syncthreads();

    const float4 q = qs[tid];
    const float ax = -2.0f * q.x, ay = -2.0f * q.y, az = -2.0f * q.z;

    float m0 = 3.4e38f, m1 = 3.4e38f;     // (cn - 2 q.c); +qn deferred
    #pragma unroll 8
    for (int m = 0; m < CWIN; m += 2) {
        const float4 ca = sc[m];           // warp-uniform broadcast LDS.128
        const float4 cb = sc[m + 1];
        float t0 = fmaf(az, ca.z, ca.w);
        float t1 = fmaf(az, cb.z, cb.w);
        t0 = fmaf(ay, ca.y, t0);
        t1 = fmaf(ay, cb.y, t1);
        t0 = fmaf(ax, ca.x, t0);
        t1 = fmaf(ax, cb.x, t1);
        m0 = fminf(m0, t0);
        m1 = fminf(m1, t1);
    }
    const float d = fminf(m0, m1) + q.w;

    // Excluded left points: x <= el; excluded right: x >= er.
    const float el = XMIN + (float)(bucket_of(sc[0].x) + 1) * BH;
    const float er = XMIN + (float)bucket_of(sc[CWIN - 1].x) * BH;
    const bool lok = (c0 == 0);
    const bool rok = (c0 + CWIN >= NPTS);

    const bool safe = (lok || (q.x >= el && (q.x - el) * (q.x - el) >= d)) &&
                      (rok || (q.x <= er && (er - q.x) * (er - q.x) >= d));

    if (!safe) {
        g_best[dir][b * NPTS + qbase + tid] = d;
        g_fail[atomicAdd(&g_nfail, 1)] = dir * TOTAL + b * NPTS + qbase + tid;
    }

    float contrib = safe ? d : 0.0f;
    #pragma unroll
    for (int o = 16; o; o >>= 1) contrib += __shfl_down_sync(0xffffffffu, contrib, o);
    if (lane == 0) spart[warp] = contrib;
    __syncthreads();
    if (tid == 0) {
        float tot = 0.0f;
        #pragma unroll
        for (int w = 0; w < NTHREADS / 32; w++) tot += spart[w];
        atomicAdd(out, tot * SCALE);
    }
}

// One warp per failed query: scan only the contiguous range that can beat
// the window bound (|dx| < sqrt(bestd)); add final value to the sum.
__global__ __launch_bounds__(FB_THREADS) void fallback_kernel(float* __restrict__ out) {
    const int gw = (blockIdx.x * FB_THREADS + threadIdx.x) >> 5;
    const int lane = threadIdx.x & 31;
    const int nf = g_nfail;

    float acc = 0.0f;
    for (int f = gw; f < nf; f += FB_WARPS) {
        const int g = g_fail[f];
        const int dir = g / TOTAL;
        const int rem = g - dir * TOTAL;
        const int b = rem / NPTS;

        const float4 q = g_sorted[dir][rem];
        const float bestd = g_best[dir][rem];
        const float4* __restrict__ cand = &g_sorted[dir ^ 1][b * NPTS];
        const int* __restrict__ off = g_off[dir ^ 1][b];

        const float s = sqrtf(bestd);
        const int lo = off[bucket_of(q.x - s)];
        const int hi = off[bucket_of(q.x + s) + 1];

        const float ax = -2.0f * q.x, ay = -2.0f * q.y, az = -2.0f * q.z;
        float best = bestd - q.w;
        for (int i = lo + lane; i < hi; i += 32) {
            float4 c = cand[i];
            float t = fmaf(az, c.z, c.w);
            t = fmaf(ay, c.y, t);
            t = fmaf(ax, c.x, t);
            best = fminf(best, t);
        }
        #pragma unroll
        for (int o = 16; o; o >>= 1)
            best = fminf(best, __shfl_xor_sync(0xffffffffu, best, o));
        if (lane == 0) acc += best + q.w;
    }
    if (acc != 0.0f) atomicAdd(out, acc * SCALE);
}

extern "C" void kernel_launch(void* const* d_in, const int* in_sizes, int n_in,
                              void* d_out, int out_size) {
    const float* p1 = (const float*)d_in[0];
    const float* p2 = (const float*)d_in[1];
    float* out = (float*)d_out;

    dim3 bgrid(NSEG, 2 * BATCH);
    hist_kernel<<<bgrid, 1024>>>(p1, p2);
    scan_kernel<<<2 * BATCH, 1024>>>(out);
    scatter_kernel<<<bgrid, 1024>>>(p1, p2);
    dim3 ngrid(NPTS / QB, BATCH, 2);
    nn_kernel<<<ngrid, NTHREADS>>>(out);
    fallback_kernel<<<FB_BLOCKS, FB_THREADS>>>(out);
}

// round 11
// speedup vs baseline: 1.0687x; 1.0687x over previous
#include <cuda_runtime.h>

#define BATCH  4
#define NPTS   8192
#define TOTAL  (BATCH * NPTS)
#define NB     1024
#define NSEG   8
#define XMIN   (-5.0f)
#define BH     (10.0f / (float)NB)
#define INVH   ((float)NB / 10.0f)

#define QB       256     // queries per nn block
#define CWIN     1280    // full certification window
#define HWIN     (CWIN / 2)   // half-window per nn block
#define NTHREADS 128     // nn threads: 2 queries per thread

#define FB_BLOCKS  256
#define FB_THREADS 256
#define FB_WARPS   (FB_BLOCKS * FB_THREADS / 32)

#define SCALE (1.0f / (float)TOTAL)

// Scratch (__device__ globals — no allocation allowed):
__device__ float4   g_sorted[2][TOTAL];        // (x,y,z,|p|^2), bucket-sorted by x
__device__ int      g_seghist[8][NSEG][NB];
__device__ int      g_segbase[8][NSEG][NB];
__device__ int      g_off[2][BATCH][NB + 1];
__device__ unsigned g_bestbits[2][TOTAL];      // merged window min (float bits, >=0)
__device__ int      g_nfail;
__device__ int      g_fail[2 * TOTAL];

__device__ __forceinline__ int bucket_of(float x) {
    int b = (int)floorf((x - XMIN) * INVH);
    return min(max(b, 0), NB - 1);
}

// grid (NSEG, 8 ab-pairs) x 1024: smem histogram per segment.
__global__ __launch_bounds__(1024) void hist_kernel(const float* __restrict__ p1,
                                                    const float* __restrict__ p2) {
    __shared__ int s[NB];
    const int ab = blockIdx.y;
    const int a = ab >> 2, b = ab & 3;
    const float* __restrict__ src = (a ? p2 : p1) + (b * NPTS + blockIdx.x * 1024) * 3;
    const int t = threadIdx.x;

    s[t] = 0;
    __syncthreads();
    atomicAdd(&s[bucket_of(src[3 * t])], 1);
    __syncthreads();
    g_seghist[ab][blockIdx.x][t] = s[t];
}

// One block per ab: cross-segment bucket scan -> segment bases. Also inits g_bestbits.
__global__ __launch_bounds__(1024) void scan_kernel(float* __restrict__ out) {
    __shared__ int wsum[32];
    const int ab = blockIdx.x;
    const int a = ab >> 2, b = ab & 3;
    const int t = threadIdx.x;
    const int lane = t & 31, warp = t >> 5;

    int segc[NSEG];
    int cnt = 0;
    #pragma unroll
    for (int s = 0; s < NSEG; s++) {
        segc[s] = g_seghist[ab][s][t];
        cnt += segc[s];
    }

    int v = cnt;
    #pragma unroll
    for (int o = 1; o < 32; o <<= 1) {
        int u = __shfl_up_sync(0xffffffffu, v, o);
        if (lane >= o) v += u;
    }
    if (lane == 31) wsum[warp] = v;
    __syncthreads();
    if (t < 32) {
        int w = wsum[t];
        #pragma unroll
        for (int o = 1; o < 32; o <<= 1) {
            int u = __shfl_up_sync(0xffffffffu, w, o);
            if (t >= o) w += u;
        }
        wsum[t] = w;
    }
    __syncthreads();
    const int incl = v + (warp ? wsum[warp - 1] : 0);
    int base = incl - cnt;
    g_off[a][b][t] = base;
    if (t == NB - 1) g_off[a][b][NB] = incl;
    if (ab == 0 && t == 0) { g_nfail = 0; out[0] = 0.0f; }

    #pragma unroll
    for (int s = 0; s < NSEG; s++) {
        g_segbase[ab][s][t] = base;
        base += segc[s];
    }

    // init merged-min array (+inf)
    unsigned* bb = (unsigned*)g_bestbits;
    #pragma unroll
    for (int k = 0; k < (2 * TOTAL) / (8 * 1024); k++)
        bb[ab * 1024 + t + k * 8192] = 0x7f800000u;
}

// grid (NSEG, 8 ab) x 1024: rank via smem atomics over segment bases.
__global__ __launch_bounds__(1024) void scatter_kernel(const float* __restrict__ p1,
                                                       const float* __restrict__ p2) {
    __shared__ int cur[NB];
    const int ab = blockIdx.y;
    const int a = ab >> 2, b = ab & 3;
    const float* __restrict__ src = (a ? p2 : p1) + (b * NPTS + blockIdx.x * 1024) * 3;
    const int t = threadIdx.x;

    cur[t] = g_segbase[ab][blockIdx.x][t];
    __syncthreads();

    float x = src[3 * t], y = src[3 * t + 1], z = src[3 * t + 2];
    float w = fmaf(x, x, fmaf(y, y, z * z));
    int pos = atomicAdd(&cur[bucket_of(x)], 1);
    g_sorted[a][b * NPTS + pos] = make_float4(x, y, z, w);
}

// grid (NPTS/QB, BATCH, 4): z = dir*2 + w. Block scans half-window w of the
// full CWIN window; partial mins merged via atomicMin on g_bestbits.
__global__ __launch_bounds__(NTHREADS) void nn_kernel() {
    __shared__ float4 sc[HWIN];    // 10 KB
    __shared__ int s_c0;

    const int dir = blockIdx.z >> 1;
    const int w   = blockIdx.z & 1;
    const int b   = blockIdx.y;
    const int qbase = blockIdx.x * QB;
    const int tid = threadIdx.x;

    const float4* __restrict__ qs   = &g_sorted[dir][b * NPTS] + qbase;
    const float4* __restrict__ cand = &g_sorted[dir ^ 1][b * NPTS];
    const int*    __restrict__ off  = g_off[dir ^ 1][b];

    if (tid == 0) {
        int c0 = off[bucket_of(qs[QB / 2].x)] - CWIN / 2;
        s_c0 = max(0, min(c0, NPTS - CWIN));
    }
    __syncthreads();
    const int base = s_c0 + w * HWIN;

    #pragma unroll
    for (int j = tid; j < HWIN; j += NTHREADS)
        sc[j] = cand[base + j];
    __syncthreads();

    const float4 q0 = qs[tid];
    const float4 q1 = qs[tid + NTHREADS];
    const float ax = -2.0f * q0.x, ay = -2.0f * q0.y, az = -2.0f * q0.z;
    const float bx = -2.0f * q1.x, by = -2.0f * q1.y, bz = -2.0f * q1.z;

    float m0 = 3.4e38f, m1 = 3.4e38f;    // (cn - 2 q.c); +qn deferred
    #pragma unroll 8
    for (int m = 0; m < HWIN; m++) {
        const float4 c = sc[m];           // warp-uniform broadcast LDS.128
        float t0 = fmaf(az, c.z, c.w);
        float t1 = fmaf(bz, c.z, c.w);
        t0 = fmaf(ay, c.y, t0);
        t1 = fmaf(by, c.y, t1);
        t0 = fmaf(ax, c.x, t0);
        t1 = fmaf(bx, c.x, t1);
        m0 = fminf(m0, t0);
        m1 = fminf(m1, t1);
    }
    const float d0 = fmaxf(m0 + q0.w, 0.0f);   // clamp: keep uint ordering valid
    const float d1 = fmaxf(m1 + q1.w, 0.0f);

    unsigned* bb = &g_bestbits[dir][b * NPTS + qbase];
    atomicMin(&bb[tid], __float_as_uint(d0));
    atomicMin(&bb[tid + NTHREADS], __float_as_uint(d1));
}

// grid (NPTS/QB, BATCH, 2) x 256: certify merged mins, sum safe, push fails.
__global__ __launch_bounds__(QB) void certify_kernel(float* __restrict__ out) {
    __shared__ float s_el, s_er;
    __shared__ int s_c0;
    __shared__ float spart[QB / 32];

    const int dir = blockIdx.z;
    const int b   = blockIdx.y;
    const int qbase = blockIdx.x * QB;
    const int tid = threadIdx.x;
    const int lane = tid & 31, warp = tid >> 5;

    const float4* __restrict__ qs   = &g_sorted[dir][b * NPTS] + qbase;
    const float4* __restrict__ cand = &g_sorted[dir ^ 1][b * NPTS];
    const int*    __restrict__ off  = g_off[dir ^ 1][b];

    if (tid == 0) {
        int c0 = off[bucket_of(qs[QB / 2].x)] - CWIN / 2;
        c0 = max(0, min(c0, NPTS - CWIN));
        s_c0 = c0;
        s_el = XMIN + (float)(bucket_of(cand[c0].x) + 1) * BH;
        s_er = XMIN + (float)bucket_of(cand[c0 + CWIN - 1].x) * BH;
    }
    __syncthreads();
    const int c0 = s_c0;
    const float el = s_el, er = s_er;
    const bool lok = (c0 == 0);
    const bool rok = (c0 + CWIN >= NPTS);

    const float qx = qs[tid].x;
    const float d = __uint_as_float(g_bestbits[dir][b * NPTS + qbase + tid]);

    const bool safe = (lok || (qx >= el && (qx - el) * (qx - el) >= d)) &&
                      (rok || (qx <= er && (er - qx) * (er - qx) >= d));

    if (!safe)
        g_fail[atomicAdd(&g_nfail, 1)] = dir * TOTAL + b * NPTS + qbase + tid;

    float contrib = safe ? d : 0.0f;
    #pragma unroll
    for (int o = 16; o; o >>= 1) contrib += __shfl_down_sync(0xffffffffu, contrib, o);
    if (lane == 0) spart[warp] = contrib;
    __syncthreads();
    if (tid == 0) {
        float tot = 0.0f;
        #pragma unroll
        for (int w = 0; w < QB / 32; w++) tot += spart[w];
        atomicAdd(out, tot * SCALE);
    }
}

// One warp per failed query: scan the contiguous range that can beat the
// window bound (|dx| < sqrt(bestd)); add final value to the sum.
__global__ __launch_bounds__(FB_THREADS) void fallback_kernel(float* __restrict__ out) {
    const int gw = (blockIdx.x * FB_THREADS + threadIdx.x) >> 5;
    const int lane = threadIdx.x & 31;
    const int nf = g_nfail;

    float acc = 0.0f;
    for (int f = gw; f < nf; f += FB_WARPS) {
        const int g = g_fail[f];
        const int dir = g / TOTAL;
        const int rem = g - dir * TOTAL;
        const int b = rem / NPTS;

        const float4 q = g_sorted[dir][rem];
        const float bestd = __uint_as_float(g_bestbits[dir][rem]);
        const float4* __restrict__ cand = &g_sorted[dir ^ 1][b * NPTS];
        const int* __restrict__ off = g_off[dir ^ 1][b];

        const float s = sqrtf(bestd);
        const int lo = off[bucket_of(q.x - s)];
        const int hi = off[bucket_of(q.x + s) + 1];

        const float ax = -2.0f * q.x, ay = -2.0f * q.y, az = -2.0f * q.z;
        float best = bestd - q.w;
        for (int i = lo + lane; i < hi; i += 32) {
            float4 c = cand[i];
            float t = fmaf(az, c.z, c.w);
            t = fmaf(ay, c.y, t);
            t = fmaf(ax, c.x, t);
            best = fminf(best, t);
        }
        #pragma unroll
        for (int o = 16; o; o >>= 1)
            best = fminf(best, __shfl_xor_sync(0xffffffffu, best, o));
        if (lane == 0) acc += best + q.w;
    }
    if (acc != 0.0f) atomicAdd(out, acc * SCALE);
}

extern "C" void kernel_launch(void* const* d_in, const int* in_sizes, int n_in,
                              void* d_out, int out_size) {
    const float* p1 = (const float*)d_in[0];
    const float* p2 = (const float*)d_in[1];
    float* out = (float*)d_out;

    dim3 bgrid(NSEG, 2 * BATCH);
    hist_kernel<<<bgrid, 1024>>>(p1, p2);
    scan_kernel<<<2 * BATCH, 1024>>>(out);
    scatter_kernel<<<bgrid, 1024>>>(p1, p2);
    dim3 ngrid(NPTS / QB, BATCH, 4);
    nn_kernel<<<ngrid, NTHREADS>>>();
    dim3 cgrid(NPTS / QB, BATCH, 2);
    certify_kernel<<<cgrid, QB>>>(out);
    fallback_kernel<<<FB_BLOCKS, FB_THREADS>>>(out);
}

// round 12
// speedup vs baseline: 1.0917x; 1.0215x over previous
#include <cuda_runtime.h>

#define BATCH  4
#define NPTS   8192
#define TOTAL  (BATCH * NPTS)
#define NB     1024
#define NSEG   8
#define XMIN   (-5.0f)
#define BH     (10.0f / (float)NB)
#define INVH   ((float)NB / 10.0f)

#define QB       256          // queries per nn block
#define CWIN     1280         // full certification window
#define HWIN     (CWIN / 2)   // half-window per nn block
#define NTHREADS 128          // nn threads: 2 queries per thread

#define FB_BLOCKS  256
#define FB_THREADS 256
#define FB_WARPS   (FB_BLOCKS * FB_THREADS / 32)

#define SCALE (1.0f / (float)TOTAL)

// Scratch (__device__ globals — no allocation allowed):
__device__ float4   g_sorted[2][TOTAL];        // (x,y,z,|p|^2), bucket-sorted by x
__device__ int      g_seghist[8][NSEG][NB];
__device__ int      g_segbase[8][NSEG][NB];
__device__ int      g_off[2][BATCH][NB + 1];
__device__ unsigned g_bestbits[2][TOTAL];      // merged window min (float bits, >=0)
__device__ int      g_nfail;
__device__ int      g_fail[2 * TOTAL];

__device__ __forceinline__ int bucket_of(float x) {
    int b = (int)floorf((x - XMIN) * INVH);
    return min(max(b, 0), NB - 1);
}

// grid (NSEG, 8 ab-pairs) x 1024: smem histogram per segment.
__global__ __launch_bounds__(1024) void hist_kernel(const float* __restrict__ p1,
                                                    const float* __restrict__ p2) {
    __shared__ int s[NB];
    const int ab = blockIdx.y;
    const int a = ab >> 2, b = ab & 3;
    const float* __restrict__ src = (a ? p2 : p1) + (b * NPTS + blockIdx.x * 1024) * 3;
    const int t = threadIdx.x;

    s[t] = 0;
    __syncthreads();
    atomicAdd(&s[bucket_of(src[3 * t])], 1);
    __syncthreads();
    g_seghist[ab][blockIdx.x][t] = s[t];
}

// One block per ab: cross-segment bucket scan -> segment bases. Also inits g_bestbits.
__global__ __launch_bounds__(1024) void scan_kernel(float* __restrict__ out) {
    __shared__ int wsum[32];
    const int ab = blockIdx.x;
    const int a = ab >> 2, b = ab & 3;
    const int t = threadIdx.x;
    const int lane = t & 31, warp = t >> 5;

    int segc[NSEG];
    int cnt = 0;
    #pragma unroll
    for (int s = 0; s < NSEG; s++) {
        segc[s] = g_seghist[ab][s][t];
        cnt += segc[s];
    }

    int v = cnt;
    #pragma unroll
    for (int o = 1; o < 32; o <<= 1) {
        int u = __shfl_up_sync(0xffffffffu, v, o);
        if (lane >= o) v += u;
    }
    if (lane == 31) wsum[warp] = v;
    __syncthreads();
    if (t < 32) {
        int w = wsum[t];
        #pragma unroll
        for (int o = 1; o < 32; o <<= 1) {
            int u = __shfl_up_sync(0xffffffffu, w, o);
            if (t >= o) w += u;
        }
        wsum[t] = w;
    }
    __syncthreads();
    const int incl = v + (warp ? wsum[warp - 1] : 0);
    int base = incl - cnt;
    g_off[a][b][t] = base;
    if (t == NB - 1) g_off[a][b][NB] = incl;
    if (ab == 0 && t == 0) { g_nfail = 0; out[0] = 0.0f; }

    #pragma unroll
    for (int s = 0; s < NSEG; s++) {
        g_segbase[ab][s][t] = base;
        base += segc[s];
    }

    // init merged-min array (+inf)
    unsigned* bb = (unsigned*)g_bestbits;
    #pragma unroll
    for (int k = 0; k < (2 * TOTAL) / (8 * 1024); k++)
        bb[ab * 1024 + t + k * 8192] = 0x7f800000u;
}

// grid (NSEG, 8 ab) x 1024: rank via smem atomics over segment bases.
__global__ __launch_bounds__(1024) void scatter_kernel(const float* __restrict__ p1,
                                                       const float* __restrict__ p2) {
    __shared__ int cur[NB];
    const int ab = blockIdx.y;
    const int a = ab >> 2, b = ab & 3;
    const float* __restrict__ src = (a ? p2 : p1) + (b * NPTS + blockIdx.x * 1024) * 3;
    const int t = threadIdx.x;

    cur[t] = g_segbase[ab][blockIdx.x][t];
    __syncthreads();

    float x = src[3 * t], y = src[3 * t + 1], z = src[3 * t + 2];
    float w = fmaf(x, x, fmaf(y, y, z * z));
    int pos = atomicAdd(&cur[bucket_of(x)], 1);
    g_sorted[a][b * NPTS + pos] = make_float4(x, y, z, w);
}

// grid (NPTS/QB, BATCH, 4): z = dir*2 + w. Block scans half-window w.
// Inner loop: batch-load 8 candidates into registers, then compute 8 —
// keeps 8 LDS in flight so the 29-cyc smem latency is never exposed.
__global__ __launch_bounds__(NTHREADS) void nn_kernel() {
    __shared__ float4 sc[HWIN];    // 10 KB
    __shared__ int s_c0;

    const int dir = blockIdx.z >> 1;
    const int w   = blockIdx.z & 1;
    const int b   = blockIdx.y;
    const int qbase = blockIdx.x * QB;
    const int tid = threadIdx.x;

    const float4* __restrict__ qs   = &g_sorted[dir][b * NPTS] + qbase;
    const float4* __restrict__ cand = &g_sorted[dir ^ 1][b * NPTS];
    const int*    __restrict__ off  = g_off[dir ^ 1][b];

    if (tid == 0) {
        int c0 = off[bucket_of(qs[QB / 2].x)] - CWIN / 2;
        s_c0 = max(0, min(c0, NPTS - CWIN));
    }
    __syncthreads();
    const int base = s_c0 + w * HWIN;

    #pragma unroll
    for (int j = tid; j < HWIN; j += NTHREADS)
        sc[j] = cand[base + j];
    __syncthreads();

    const float4 q0 = qs[tid];
    const float4 q1 = qs[tid + NTHREADS];
    const float ax = -2.0f * q0.x, ay = -2.0f * q0.y, az = -2.0f * q0.z;
    const float bx = -2.0f * q1.x, by = -2.0f * q1.y, bz = -2.0f * q1.z;

    float m0 = 3.4e38f, m1 = 3.4e38f;    // (cn - 2 q.c); +qn deferred
    #pragma unroll 1
    for (int m = 0; m < HWIN; m += 8) {
        float4 cbuf[8];
        #pragma unroll
        for (int j = 0; j < 8; j++)
            cbuf[j] = sc[m + j];          // 8 broadcast LDS.128 batched up front
        #pragma unroll
        for (int j = 0; j < 8; j++) {
            const float4 c = cbuf[j];
            float t0 = fmaf(az, c.z, c.w);
            float t1 = fmaf(bz, c.z, c.w);
            t0 = fmaf(ay, c.y, t0);
            t1 = fmaf(by, c.y, t1);
            t0 = fmaf(ax, c.x, t0);
            t1 = fmaf(bx, c.x, t1);
            m0 = fminf(m0, t0);
            m1 = fminf(m1, t1);
        }
    }
    const float d0 = fmaxf(m0 + q0.w, 0.0f);   // clamp: keep uint ordering valid
    const float d1 = fmaxf(m1 + q1.w, 0.0f);

    unsigned* bb = &g_bestbits[dir][b * NPTS + qbase];
    atomicMin(&bb[tid], __float_as_uint(d0));
    atomicMin(&bb[tid + NTHREADS], __float_as_uint(d1));
}

// grid (NPTS/QB, BATCH, 2) x 256: certify merged mins, sum safe, push fails.
__global__ __launch_bounds__(QB) void certify_kernel(float* __restrict__ out) {
    __shared__ float s_el, s_er;
    __shared__ int s_c0;
    __shared__ float spart[QB / 32];

    const int dir = blockIdx.z;
    const int b   = blockIdx.y;
    const int qbase = blockIdx.x * QB;
    const int tid = threadIdx.x;
    const int lane = tid & 31, warp = tid >> 5;

    const float4* __restrict__ qs   = &g_sorted[dir][b * NPTS] + qbase;
    const float4* __restrict__ cand = &g_sorted[dir ^ 1][b * NPTS];
    const int*    __restrict__ off  = g_off[dir ^ 1][b];

    if (tid == 0) {
        int c0 = off[bucket_of(qs[QB / 2].x)] - CWIN / 2;
        c0 = max(0, min(c0, NPTS - CWIN));
        s_c0 = c0;
        s_el = XMIN + (float)(bucket_of(cand[c0].x) + 1) * BH;
        s_er = XMIN + (float)bucket_of(cand[c0 + CWIN - 1].x) * BH;
    }
    __syncthreads();
    const int c0 = s_c0;
    const float el = s_el, er = s_er;
    const bool lok = (c0 == 0);
    const bool rok = (c0 + CWIN >= NPTS);

    const float qx = qs[tid].x;
    const float d = __uint_as_float(g_bestbits[dir][b * NPTS + qbase + tid]);

    const bool safe = (lok || (qx >= el && (qx - el) * (qx - el) >= d)) &&
                      (rok || (qx <= er && (er - qx) * (er - qx) >= d));

    if (!safe)
        g_fail[atomicAdd(&g_nfail, 1)] = dir * TOTAL + b * NPTS + qbase + tid;

    float contrib = safe ? d : 0.0f;
    #pragma unroll
    for (int o = 16; o; o >>= 1) contrib += __shfl_down_sync(0xffffffffu, contrib, o);
    if (lane == 0) spart[warp] = contrib;
    __syncthreads();
    if (tid == 0) {
        float tot = 0.0f;
        #pragma unroll
        for (int w = 0; w < QB / 32; w++) tot += spart[w];
        atomicAdd(out, tot * SCALE);
    }
}

// One warp per failed query: scan the contiguous range that can beat the
// window bound (|dx| < sqrt(bestd)); add final value to the sum.
__global__ __launch_bounds__(FB_THREADS) void fallback_kernel(float* __restrict__ out) {
    const int gw = (blockIdx.x * FB_THREADS + threadIdx.x) >> 5;
    const int lane = threadIdx.x & 31;
    const int nf = g_nfail;

    float acc = 0.0f;
    for (int f = gw; f < nf; f += FB_WARPS) {
        const int g = g_fail[f];
        const int dir = g / TOTAL;
        const int rem = g - dir * TOTAL;
        const int b = rem / NPTS;

        const float4 q = g_sorted[dir][rem];
        const float bestd = __uint_as_float(g_bestbits[dir][rem]);
        const float4* __restrict__ cand = &g_sorted[dir ^ 1][b * NPTS];
        const int* __restrict__ off = g_off[dir ^ 1][b];

        const float s = sqrtf(bestd);
        const int lo = off[bucket_of(q.x - s)];
        const int hi = off[bucket_of(q.x + s) + 1];

        const float ax = -2.0f * q.x, ay = -2.0f * q.y, az = -2.0f * q.z;
        float best = bestd - q.w;
        for (int i = lo + lane; i < hi; i += 32) {
            float4 c = cand[i];
            float t = fmaf(az, c.z, c.w);
            t = fmaf(ay, c.y, t);
            t = fmaf(ax, c.x, t);
            best = fminf(best, t);
        }
        #pragma unroll
        for (int o = 16; o; o >>= 1)
            best = fminf(best, __shfl_xor_sync(0xffffffffu, best, o));
        if (lane == 0) acc += best + q.w;
    }
    if (acc != 0.0f) atomicAdd(out, acc * SCALE);
}

extern "C" void kernel_launch(void* const* d_in, const int* in_sizes, int n_in,
                              void* d_out, int out_size) {
    const float* p1 = (const float*)d_in[0];
    const float* p2 = (const float*)d_in[1];
    float* out = (float*)d_out;

    dim3 bgrid(NSEG, 2 * BATCH);
    hist_kernel<<<bgrid, 1024>>>(p1, p2);
    scan_kernel<<<2 * BATCH, 1024>>>(out);
    scatter_kernel<<<bgrid, 1024>>>(p1, p2);
    dim3 ngrid(NPTS / QB, BATCH, 4);
    nn_kernel<<<ngrid, NTHREADS>>>();
    dim3 cgrid(NPTS / QB, BATCH, 2);
    certify_kernel<<<cgrid, QB>>>(out);
    fallback_kernel<<<FB_BLOCKS, FB_THREADS>>>(out);
}

// round 13
// speedup vs baseline: 1.1223x; 1.0281x over previous
#include <cuda_runtime.h>

#define BATCH  4
#define NPTS   8192
#define TOTAL  (BATCH * NPTS)
#define NB     1024
#define NSEG   8
#define XMIN   (-5.0f)
#define BH     (10.0f / (float)NB)
#define INVH   ((float)NB / 10.0f)

#define QB       256          // queries per nn block
#define CWIN     1280         // full certification window
#define NWS      4            // window splits
#define QWIN     (CWIN / NWS) // 320 candidates per nn block
#define NTHREADS 128          // nn threads: 2 queries per thread

#define FB_BLOCKS  256
#define FB_THREADS 256
#define FB_WARPS   (FB_BLOCKS * FB_THREADS / 32)

#define SCALE (1.0f / (float)TOTAL)

// Scratch (__device__ globals — no allocation allowed):
__device__ float4   g_sorted[2][TOTAL];        // (x,y,z,|p|^2), bucket-sorted by x
__device__ int      g_seghist[8][NSEG][NB];
__device__ int      g_segbase[8][NSEG][NB];
__device__ int      g_off[2][BATCH][NB + 1];
__device__ unsigned g_bestbits[2][TOTAL];      // merged window min (float bits, >=0)
__device__ int      g_nfail;
__device__ int      g_fail[2 * TOTAL];

__device__ __forceinline__ int bucket_of(float x) {
    int b = (int)floorf((x - XMIN) * INVH);
    return min(max(b, 0), NB - 1);
}

// grid (NSEG, 8 ab-pairs) x 1024: smem histogram per segment.
__global__ __launch_bounds__(1024) void hist_kernel(const float* __restrict__ p1,
                                                    const float* __restrict__ p2) {
    __shared__ int s[NB];
    const int ab = blockIdx.y;
    const int a = ab >> 2, b = ab & 3;
    const float* __restrict__ src = (a ? p2 : p1) + (b * NPTS + blockIdx.x * 1024) * 3;
    const int t = threadIdx.x;

    s[t] = 0;
    __syncthreads();
    atomicAdd(&s[bucket_of(src[3 * t])], 1);
    __syncthreads();
    g_seghist[ab][blockIdx.x][t] = s[t];
}

// One block per ab: cross-segment bucket scan -> segment bases. Also inits g_bestbits.
__global__ __launch_bounds__(1024) void scan_kernel(float* __restrict__ out) {
    __shared__ int wsum[32];
    const int ab = blockIdx.x;
    const int a = ab >> 2, b = ab & 3;
    const int t = threadIdx.x;
    const int lane = t & 31, warp = t >> 5;

    int segc[NSEG];
    int cnt = 0;
    #pragma unroll
    for (int s = 0; s < NSEG; s++) {
        segc[s] = g_seghist[ab][s][t];
        cnt += segc[s];
    }

    int v = cnt;
    #pragma unroll
    for (int o = 1; o < 32; o <<= 1) {
        int u = __shfl_up_sync(0xffffffffu, v, o);
        if (lane >= o) v += u;
    }
    if (lane == 31) wsum[warp] = v;
    __syncthreads();
    if (t < 32) {
        int w = wsum[t];
        #pragma unroll
        for (int o = 1; o < 32; o <<= 1) {
            int u = __shfl_up_sync(0xffffffffu, w, o);
            if (t >= o) w += u;
        }
        wsum[t] = w;
    }
    __syncthreads();
    const int incl = v + (warp ? wsum[warp - 1] : 0);
    int base = incl - cnt;
    g_off[a][b][t] = base;
    if (t == NB - 1) g_off[a][b][NB] = incl;
    if (ab == 0 && t == 0) { g_nfail = 0; out[0] = 0.0f; }

    #pragma unroll
    for (int s = 0; s < NSEG; s++) {
        g_segbase[ab][s][t] = base;
        base += segc[s];
    }

    // init merged-min array (+inf)
    unsigned* bb = (unsigned*)g_bestbits;
    #pragma unroll
    for (int k = 0; k < (2 * TOTAL) / (8 * 1024); k++)
        bb[ab * 1024 + t + k * 8192] = 0x7f800000u;
}

// grid (NSEG, 8 ab) x 1024: rank via smem atomics over segment bases.
__global__ __launch_bounds__(1024) void scatter_kernel(const float* __restrict__ p1,
                                                       const float* __restrict__ p2) {
    __shared__ int cur[NB];
    const int ab = blockIdx.y;
    const int a = ab >> 2, b = ab & 3;
    const float* __restrict__ src = (a ? p2 : p1) + (b * NPTS + blockIdx.x * 1024) * 3;
    const int t = threadIdx.x;

    cur[t] = g_segbase[ab][blockIdx.x][t];
    __syncthreads();

    float x = src[3 * t], y = src[3 * t + 1], z = src[3 * t + 2];
    float w = fmaf(x, x, fmaf(y, y, z * z));
    int pos = atomicAdd(&cur[bucket_of(x)], 1);
    g_sorted[a][b * NPTS + pos] = make_float4(x, y, z, w);
}

// grid (NPTS/QB, BATCH, 2*NWS): z = dir*NWS + w. Block scans quarter-window w
// of the full CWIN window; partial mins merged via atomicMin on g_bestbits.
// 1024 blocks x 4 warps -> ~28 warps/SM for latency hiding.
__global__ __launch_bounds__(NTHREADS) void nn_kernel() {
    __shared__ float4 sc[QWIN];    // 5 KB
    __shared__ int s_c0;

    const int dir = blockIdx.z >> 2;
    const int w   = blockIdx.z & 3;
    const int b   = blockIdx.y;
    const int qbase = blockIdx.x * QB;
    const int tid = threadIdx.x;

    const float4* __restrict__ qs   = &g_sorted[dir][b * NPTS] + qbase;
    const float4* __restrict__ cand = &g_sorted[dir ^ 1][b * NPTS];
    const int*    __restrict__ off  = g_off[dir ^ 1][b];

    if (tid == 0) {
        int c0 = off[bucket_of(qs[QB / 2].x)] - CWIN / 2;
        s_c0 = max(0, min(c0, NPTS - CWIN));
    }
    __syncthreads();
    const int base = s_c0 + w * QWIN;

    #pragma unroll
    for (int j = tid; j < QWIN; j += NTHREADS)
        sc[j] = cand[base + j];
    __syncthreads();

    const float4 q0 = qs[tid];
    const float4 q1 = qs[tid + NTHREADS];
    const float ax = -2.0f * q0.x, ay = -2.0f * q0.y, az = -2.0f * q0.z;
    const float bx = -2.0f * q1.x, by = -2.0f * q1.y, bz = -2.0f * q1.z;

    float m0 = 3.4e38f, m1 = 3.4e38f;    // (cn - 2 q.c); +qn deferred
    #pragma unroll 1
    for (int m = 0; m < QWIN; m += 8) {
        float4 cbuf[8];
        #pragma unroll
        for (int j = 0; j < 8; j++)
            cbuf[j] = sc[m + j];          // broadcast LDS.128 batched up front
        #pragma unroll
        for (int j = 0; j < 8; j++) {
            const float4 c = cbuf[j];
            float t0 = fmaf(az, c.z, c.w);
            float t1 = fmaf(bz, c.z, c.w);
            t0 = fmaf(ay, c.y, t0);
            t1 = fmaf(by, c.y, t1);
            t0 = fmaf(ax, c.x, t0);
            t1 = fmaf(bx, c.x, t1);
            m0 = fminf(m0, t0);
            m1 = fminf(m1, t1);
        }
    }
    const float d0 = fmaxf(m0 + q0.w, 0.0f);   // clamp: keep uint ordering valid
    const float d1 = fmaxf(m1 + q1.w, 0.0f);

    unsigned* bb = &g_bestbits[dir][b * NPTS + qbase];
    atomicMin(&bb[tid], __float_as_uint(d0));
    atomicMin(&bb[tid + NTHREADS], __float_as_uint(d1));
}

// grid (NPTS/QB, BATCH, 2) x 256: certify merged mins, sum safe, push fails.
__global__ __launch_bounds__(QB) void certify_kernel(float* __restrict__ out) {
    __shared__ float s_el, s_er;
    __shared__ int s_c0;
    __shared__ float spart[QB / 32];

    const int dir = blockIdx.z;
    const int b   = blockIdx.y;
    const int qbase = blockIdx.x * QB;
    const int tid = threadIdx.x;
    const int lane = tid & 31, warp = tid >> 5;

    const float4* __restrict__ qs   = &g_sorted[dir][b * NPTS] + qbase;
    const float4* __restrict__ cand = &g_sorted[dir ^ 1][b * NPTS];
    const int*    __restrict__ off  = g_off[dir ^ 1][b];

    if (tid == 0) {
        int c0 = off[bucket_of(qs[QB / 2].x)] - CWIN / 2;
        c0 = max(0, min(c0, NPTS - CWIN));
        s_c0 = c0;
        s_el = XMIN + (float)(bucket_of(cand[c0].x) + 1) * BH;
        s_er = XMIN + (float)bucket_of(cand[c0 + CWIN - 1].x) * BH;
    }
    __syncthreads();
    const int c0 = s_c0;
    const float el = s_el, er = s_er;
    const bool lok = (c0 == 0);
    const bool rok = (c0 + CWIN >= NPTS);

    const float qx = qs[tid].x;
    const float d = __uint_as_float(g_bestbits[dir][b * NPTS + qbase + tid]);

    const bool safe = (lok || (qx >= el && (qx - el) * (qx - el) >= d)) &&
                      (rok || (qx <= er && (er - qx) * (er - qx) >= d));

    if (!safe)
        g_fail[atomicAdd(&g_nfail, 1)] = dir * TOTAL + b * NPTS + qbase + tid;

    float contrib = safe ? d : 0.0f;
    #pragma unroll
    for (int o = 16; o; o >>= 1) contrib += __shfl_down_sync(0xffffffffu, contrib, o);
    if (lane == 0) spart[warp] = contrib;
    __syncthreads();
    if (tid == 0) {
        float tot = 0.0f;
        #pragma unroll
        for (int w = 0; w < QB / 32; w++) tot += spart[w];
        atomicAdd(out, tot * SCALE);
    }
}

// One warp per failed query: scan the contiguous range that can beat the
// window bound (|dx| < sqrt(bestd)); add final value to the sum.
__global__ __launch_bounds__(FB_THREADS) void fallback_kernel(float* __restrict__ out) {
    const int gw = (blockIdx.x * FB_THREADS + threadIdx.x) >> 5;
    const int lane = threadIdx.x & 31;
    const int nf = g_nfail;

    float acc = 0.0f;
    for (int f = gw; f < nf; f += FB_WARPS) {
        const int g = g_fail[f];
        const int dir = g / TOTAL;
        const int rem = g - dir * TOTAL;
        const int b = rem / NPTS;

        const float4 q = g_sorted[dir][rem];
        const float bestd = __uint_as_float(g_bestbits[dir][rem]);
        const float4* __restrict__ cand = &g_sorted[dir ^ 1][b * NPTS];
        const int* __restrict__ off = g_off[dir ^ 1][b];

        const float s = sqrtf(bestd);
        const int lo = off[bucket_of(q.x - s)];
        const int hi = off[bucket_of(q.x + s) + 1];

        const float ax = -2.0f * q.x, ay = -2.0f * q.y, az = -2.0f * q.z;
        float best = bestd - q.w;
        for (int i = lo + lane; i < hi; i += 32) {
            float4 c = cand[i];
            float t = fmaf(az, c.z, c.w);
            t = fmaf(ay, c.y, t);
            t = fmaf(ax, c.x, t);
            best = fminf(best, t);
        }
        #pragma unroll
        for (int o = 16; o; o >>= 1)
            best = fminf(best, __shfl_xor_sync(0xffffffffu, best, o));
        if (lane == 0) acc += best + q.w;
    }
    if (acc != 0.0f) atomicAdd(out, acc * SCALE);
}

extern "C" void kernel_launch(void* const* d_in, const int* in_sizes, int n_in,
                              void* d_out, int out_size) {
    const float* p1 = (const float*)d_in[0];
    const float* p2 = (const float*)d_in[1];
    float* out = (float*)d_out;

    dim3 bgrid(NSEG, 2 * BATCH);
    hist_kernel<<<bgrid, 1024>>>(p1, p2);
    scan_kernel<<<2 * BATCH, 1024>>>(out);
    scatter_kernel<<<bgrid, 1024>>>(p1, p2);
    dim3 ngrid(NPTS / QB, BATCH, 2 * NWS);
    nn_kernel<<<ngrid, NTHREADS>>>();
    dim3 cgrid(NPTS / QB, BATCH, 2);
    certify_kernel<<<cgrid, QB>>>(out);
    fallback_kernel<<<FB_BLOCKS, FB_THREADS>>>(out);
}

// round 14
// speedup vs baseline: 1.1733x; 1.0454x over previous
#include <cuda_runtime.h>

#define BATCH  4
#define NPTS   8192
#define TOTAL  (BATCH * NPTS)
#define NB     1024
#define NSEG   8
#define XMIN   (-5.0f)
#define BH     (10.0f / (float)NB)
#define INVH   ((float)NB / 10.0f)

#define QB       256          // queries per certify block
#define CWIN     1280         // full certification window
#define NWS      4            // window splits
#define QWIN     (CWIN / NWS) // 320 candidates per nn block
#define NTHREADS 128          // nn threads: 2 queries per thread

#define SCALE (1.0f / (float)TOTAL)

// Scratch (__device__ globals — no allocation allowed):
__device__ float4   g_sorted[2][TOTAL];        // (x,y,z,|p|^2), bucket-sorted by x
__device__ int      g_seghist[8][NSEG][NB];
__device__ int      g_segbase[8][NSEG][NB];
__device__ int      g_off[2][BATCH][NB + 1];
__device__ unsigned g_bestbits[2][TOTAL];      // merged window min (float bits, >=0)
__device__ int      g_done[8];                 // hist completion counters (self-reset)

__device__ __forceinline__ int bucket_of(float x) {
    int b = (int)floorf((x - XMIN) * INVH);
    return min(max(b, 0), NB - 1);
}

// grid (NSEG, 8 ab-pairs) x 1024: smem histogram per segment; the LAST block
// of each ab (elected via counter) performs the cross-segment scan inline.
__global__ __launch_bounds__(1024) void hist_scan_kernel(const float* __restrict__ p1,
                                                         const float* __restrict__ p2,
                                                         float* __restrict__ out) {
    __shared__ int s[NB];
    __shared__ int wsum[32];
    __shared__ int s_last;

    const int ab = blockIdx.y;
    const int a = ab >> 2, b = ab & 3;
    const float* __restrict__ src = (a ? p2 : p1) + (b * NPTS + blockIdx.x * 1024) * 3;
    const int t = threadIdx.x;
    const int lane = t & 31, warp = t >> 5;

    s[t] = 0;
    __syncthreads();
    atomicAdd(&s[bucket_of(src[3 * t])], 1);
    __syncthreads();
    g_seghist[ab][blockIdx.x][t] = s[t];

    // Elect the last-finishing block of this ab to run the scan.
    if (t == 0) {
        __threadfence();
        s_last = (atomicAdd(&g_done[ab], 1) == NSEG - 1) ? 1 : 0;
    }
    __syncthreads();
    if (!s_last) return;

    // ---- scan (runs once per ab) ----
    int segc[NSEG];
    int cnt = 0;
    #pragma unroll
    for (int sg = 0; sg < NSEG; sg++) {
        segc[sg] = g_seghist[ab][sg][t];
        cnt += segc[sg];
    }

    int v = cnt;
    #pragma unroll
    for (int o = 1; o < 32; o <<= 1) {
        int u = __shfl_up_sync(0xffffffffu, v, o);
        if (lane >= o) v += u;
    }
    if (lane == 31) wsum[warp] = v;
    __syncthreads();
    if (t < 32) {
        int w = wsum[t];
        #pragma unroll
        for (int o = 1; o < 32; o <<= 1) {
            int u = __shfl_up_sync(0xffffffffu, w, o);
            if (t >= o) w += u;
        }
        wsum[t] = w;
    }
    __syncthreads();
    const int incl = v + (warp ? wsum[warp - 1] : 0);
    int base = incl - cnt;
    g_off[a][b][t] = base;
    if (t == NB - 1) g_off[a][b][NB] = incl;
    if (ab == 0 && t == 0) out[0] = 0.0f;

    #pragma unroll
    for (int sg = 0; sg < NSEG; sg++) {
        g_segbase[ab][sg][t] = base;
        base += segc[sg];
    }

    // init merged-min slice (+inf)
    unsigned* bb = (unsigned*)g_bestbits;
    #pragma unroll
    for (int k = 0; k < (2 * TOTAL) / (8 * 1024); k++)
        bb[ab * 1024 + t + k * 8192] = 0x7f800000u;

    if (t == 0) g_done[ab] = 0;   // reset for next graph replay
}

// grid (NSEG, 8 ab) x 1024: rank via smem atomics over segment bases.
__global__ __launch_bounds__(1024) void scatter_kernel(const float* __restrict__ p1,
                                                       const float* __restrict__ p2) {
    __shared__ int cur[NB];
    const int ab = blockIdx.y;
    const int a = ab >> 2, b = ab & 3;
    const float* __restrict__ src = (a ? p2 : p1) + (b * NPTS + blockIdx.x * 1024) * 3;
    const int t = threadIdx.x;

    cur[t] = g_segbase[ab][blockIdx.x][t];
    __syncthreads();

    float x = src[3 * t], y = src[3 * t + 1], z = src[3 * t + 2];
    float w = fmaf(x, x, fmaf(y, y, z * z));
    int pos = atomicAdd(&cur[bucket_of(x)], 1);
    g_sorted[a][b * NPTS + pos] = make_float4(x, y, z, w);
}

// grid (NPTS/QB, BATCH, 2*NWS): z = dir*NWS + w. Block scans quarter-window w;
// partial mins merged via atomicMin on g_bestbits.
__global__ __launch_bounds__(NTHREADS) void nn_kernel() {
    __shared__ float4 sc[QWIN];    // 5 KB
    __shared__ int s_c0;

    const int dir = blockIdx.z >> 2;
    const int w   = blockIdx.z & 3;
    const int b   = blockIdx.y;
    const int qbase = blockIdx.x * QB;
    const int tid = threadIdx.x;

    const float4* __restrict__ qs   = &g_sorted[dir][b * NPTS] + qbase;
    const float4* __restrict__ cand = &g_sorted[dir ^ 1][b * NPTS];
    const int*    __restrict__ off  = g_off[dir ^ 1][b];

    if (tid == 0) {
        int c0 = off[bucket_of(qs[QB / 2].x)] - CWIN / 2;
        s_c0 = max(0, min(c0, NPTS - CWIN));
    }
    __syncthreads();
    const int base = s_c0 + w * QWIN;

    #pragma unroll
    for (int j = tid; j < QWIN; j += NTHREADS)
        sc[j] = cand[base + j];
    __syncthreads();

    const float4 q0 = qs[tid];
    const float4 q1 = qs[tid + NTHREADS];
    const float ax = -2.0f * q0.x, ay = -2.0f * q0.y, az = -2.0f * q0.z;
    const float bx = -2.0f * q1.x, by = -2.0f * q1.y, bz = -2.0f * q1.z;

    float m0 = 3.4e38f, m1 = 3.4e38f;    // (cn - 2 q.c); +qn deferred
    #pragma unroll 1
    for (int m = 0; m < QWIN; m += 8) {
        float4 cbuf[8];
        #pragma unroll
        for (int j = 0; j < 8; j++)
            cbuf[j] = sc[m + j];          // broadcast LDS.128 batched up front
        #pragma unroll
        for (int j = 0; j < 8; j++) {
            const float4 c = cbuf[j];
            float t0 = fmaf(az, c.z, c.w);
            float t1 = fmaf(bz, c.z, c.w);
            t0 = fmaf(ay, c.y, t0);
            t1 = fmaf(by, c.y, t1);
            t0 = fmaf(ax, c.x, t0);
            t1 = fmaf(bx, c.x, t1);
            m0 = fminf(m0, t0);
            m1 = fminf(m1, t1);
        }
    }
    const float d0 = fmaxf(m0 + q0.w, 0.0f);   // clamp: keep uint ordering valid
    const float d1 = fmaxf(m1 + q1.w, 0.0f);

    unsigned* bb = &g_bestbits[dir][b * NPTS + qbase];
    atomicMin(&bb[tid], __float_as_uint(d0));
    atomicMin(&bb[tid + NTHREADS], __float_as_uint(d1));
}

// grid (NPTS/QB, BATCH, 2) x 256: certify merged mins, sum safe, and handle
// this block's failures in-place (block-local list, one warp per failure).
__global__ __launch_bounds__(QB) void certify_fb_kernel(float* __restrict__ out) {
    __shared__ float s_el, s_er;
    __shared__ int s_c0;
    __shared__ float spart[QB / 32];
    __shared__ int   fidx[QB];      // failed query tids
    __shared__ float fbst[QB];      // their window bounds
    __shared__ int   s_nf;

    const int dir = blockIdx.z;
    const int b   = blockIdx.y;
    const int qbase = blockIdx.x * QB;
    const int tid = threadIdx.x;
    const int lane = tid & 31, warp = tid >> 5;

    const float4* __restrict__ qs   = &g_sorted[dir][b * NPTS] + qbase;
    const float4* __restrict__ cand = &g_sorted[dir ^ 1][b * NPTS];
    const int*    __restrict__ off  = g_off[dir ^ 1][b];

    if (tid == 0) {
        int c0 = off[bucket_of(qs[QB / 2].x)] - CWIN / 2;
        c0 = max(0, min(c0, NPTS - CWIN));
        s_c0 = c0;
        s_el = XMIN + (float)(bucket_of(cand[c0].x) + 1) * BH;
        s_er = XMIN + (float)bucket_of(cand[c0 + CWIN - 1].x) * BH;
        s_nf = 0;
    }
    __syncthreads();
    const int c0 = s_c0;
    const float el = s_el, er = s_er;
    const bool lok = (c0 == 0);
    const bool rok = (c0 + CWIN >= NPTS);

    const float qx = qs[tid].x;
    const float d = __uint_as_float(g_bestbits[dir][b * NPTS + qbase + tid]);

    const bool safe = (lok || (qx >= el && (qx - el) * (qx - el) >= d)) &&
                      (rok || (qx <= er && (er - qx) * (er - qx) >= d));

    if (!safe) {
        int i = atomicAdd(&s_nf, 1);
        fidx[i] = tid;
        fbst[i] = d;
    }

    float contrib = safe ? d : 0.0f;
    #pragma unroll
    for (int o = 16; o; o >>= 1) contrib += __shfl_down_sync(0xffffffffu, contrib, o);
    if (lane == 0) spart[warp] = contrib;
    __syncthreads();

    // ---- in-block fallback: one warp per failed query ----
    const int nf = s_nf;
    float acc = 0.0f;
    for (int f = warp; f < nf; f += QB / 32) {
        const int qt = fidx[f];
        const float bestd = fbst[f];
        const float4 q = qs[qt];

        const float s = sqrtf(bestd);
        const int lo = off[bucket_of(q.x - s)];
        const int hi = off[bucket_of(q.x + s) + 1];

        const float ax = -2.0f * q.x, ay = -2.0f * q.y, az = -2.0f * q.z;
        float best = bestd - q.w;
        for (int i = lo + lane; i < hi; i += 32) {
            float4 c = cand[i];
            float t = fmaf(az, c.z, c.w);
            t = fmaf(ay, c.y, t);
            t = fmaf(ax, c.x, t);
            best = fminf(best, t);
        }
        #pragma unroll
        for (int o = 16; o; o >>= 1)
            best = fminf(best, __shfl_xor_sync(0xffffffffu, best, o));
        if (lane == 0) acc += best + q.w;
    }
    if (lane == 0 && acc != 0.0f) spart[warp] += acc;
    __syncthreads();

    if (tid == 0) {
        float tot = 0.0f;
        #pragma unroll
        for (int w = 0; w < QB / 32; w++) tot += spart[w];
        atomicAdd(out, tot * SCALE);
    }
}

extern "C" void kernel_launch(void* const* d_in, const int* in_sizes, int n_in,
                              void* d_out, int out_size) {
    const float* p1 = (const float*)d_in[0];
    const float* p2 = (const float*)d_in[1];
    float* out = (float*)d_out;

    dim3 bgrid(NSEG, 2 * BATCH);
    hist_scan_kernel<<<bgrid, 1024>>>(p1, p2, out);
    scatter_kernel<<<bgrid, 1024>>>(p1, p2);
    dim3 ngrid(NPTS / QB, BATCH, 2 * NWS);
    nn_kernel<<<ngrid, NTHREADS>>>();
    dim3 cgrid(NPTS / QB, BATCH, 2);
    certify_fb_kernel<<<cgrid, QB>>>(out);
}